// round 1
// baseline (speedup 1.0000x reference)
#include <cuda_runtime.h>
#include <cstddef>

// ---------------------------------------------------------------------------
// BiAffine: two cross-attentions.
//   Path1: Q1 = S1@W1 ; P1 = softmax(Q1 S2^T) ; out1 = P1 @ S2
//   Path2: Q2 = S2@W2 ; P2 = softmax(Q2 S1^T) ; out2 = P2 @ S1
// b=8, n=2048, h=1024.  Output = concat(out1, out2), fp32.
// ---------------------------------------------------------------------------

#define BM 128
#define BN 128
#define BK 16

// Static device scratch (allocation-free per harness rules).
__device__ float g_Q[8LL * 2048 * 1024];      //  67 MB
__device__ float g_P[8LL * 2048 * 2048];      // 134 MB

__device__ __forceinline__ void st_trans4(float* dstRow0, int rowStride, float4 v) {
    // dstRow0 points at [k][m]; store v into rows k..k+3 at column offset 0
    dstRow0[0 * rowStride] = v.x;
    dstRow0[1 * rowStride] = v.y;
    dstRow0[2 * rowStride] = v.z;
    dstRow0[3 * rowStride] = v.w;
}

// C[M,N] = A[M,K] @ op(B),  op(B) = B[K,N] (TRANSB=false) or B[N,K]^T (TRANSB=true)
// Batched via blockIdx.z with element strides sA/sB/sC.
template <bool TRANSB>
__global__ void __launch_bounds__(256, 2)
sgemm_kernel(const float* __restrict__ A, const float* __restrict__ B,
             float* __restrict__ C, int M, int N, int K,
             long long sA, long long sB, long long sC)
{
    const float* Ab = A + (long long)blockIdx.z * sA;
    const float* Bb = B + (long long)blockIdx.z * sB;
    float*       Cb = C + (long long)blockIdx.z * sC;

    __shared__ float As[2][BK][BM + 4];
    __shared__ float Bs[2][BK][BN + 4];

    const int tid = threadIdx.x;
    const int tx  = tid & 15;        // 0..15  -> N direction (8 cols each)
    const int ty  = tid >> 4;        // 0..15  -> M direction (8 rows each)
    const int bm  = blockIdx.y * BM;
    const int bn  = blockIdx.x * BN;

    // --- per-thread global-load coordinates -------------------------------
    // A tile (BM x BK): 512 float4; thread handles rows a_m and a_m+64
    const int a_m = tid >> 2;             // 0..63
    const int a_k = (tid & 3) << 2;       // 0,4,8,12
    // B tile, no-trans (BK x BN): thread handles k rows b_k and b_k+8
    const int b_k = tid >> 5;             // 0..7
    const int b_n = (tid & 31) << 2;      // 0..124
    // B tile, trans (load from B[N,K]): thread handles n rows t_n and t_n+64
    const int t_n = tid >> 2;             // 0..63
    const int t_k = (tid & 3) << 2;       // 0,4,8,12

    float acc[8][8];
#pragma unroll
    for (int i = 0; i < 8; i++)
#pragma unroll
        for (int j = 0; j < 8; j++) acc[i][j] = 0.0f;

    const int nk = K / BK;

    // ---- preload tile 0 into buffer 0 ------------------------------------
    {
        float4 va0 = *(const float4*)&Ab[(size_t)(bm + a_m)      * K + a_k];
        float4 va1 = *(const float4*)&Ab[(size_t)(bm + a_m + 64) * K + a_k];
        st_trans4(&As[0][a_k][a_m],      BM + 4, va0);
        st_trans4(&As[0][a_k][a_m + 64], BM + 4, va1);
        if (TRANSB) {
            float4 vb0 = *(const float4*)&Bb[(size_t)(bn + t_n)      * K + t_k];
            float4 vb1 = *(const float4*)&Bb[(size_t)(bn + t_n + 64) * K + t_k];
            st_trans4(&Bs[0][t_k][t_n],      BN + 4, vb0);
            st_trans4(&Bs[0][t_k][t_n + 64], BN + 4, vb1);
        } else {
            float4 vb0 = *(const float4*)&Bb[(size_t)(b_k)     * N + bn + b_n];
            float4 vb1 = *(const float4*)&Bb[(size_t)(b_k + 8) * N + bn + b_n];
            *(float4*)&Bs[0][b_k][b_n]     = vb0;
            *(float4*)&Bs[0][b_k + 8][b_n] = vb1;
        }
    }
    __syncthreads();

    int buf = 0;
    for (int t = 0; t < nk; t++) {
        float4 pa0, pa1, pb0, pb1;
        const bool has_next = (t + 1 < nk);
        if (has_next) {
            const int kk = (t + 1) * BK;
            pa0 = *(const float4*)&Ab[(size_t)(bm + a_m)      * K + kk + a_k];
            pa1 = *(const float4*)&Ab[(size_t)(bm + a_m + 64) * K + kk + a_k];
            if (TRANSB) {
                pb0 = *(const float4*)&Bb[(size_t)(bn + t_n)      * K + kk + t_k];
                pb1 = *(const float4*)&Bb[(size_t)(bn + t_n + 64) * K + kk + t_k];
            } else {
                pb0 = *(const float4*)&Bb[(size_t)(kk + b_k)     * N + bn + b_n];
                pb1 = *(const float4*)&Bb[(size_t)(kk + b_k + 8) * N + bn + b_n];
            }
        }

        // ---- compute on current buffer -----------------------------------
#pragma unroll
        for (int k = 0; k < BK; k++) {
            float a[8], b[8];
            float4 v;
            v = *(const float4*)&As[buf][k][ty * 8];     a[0]=v.x; a[1]=v.y; a[2]=v.z; a[3]=v.w;
            v = *(const float4*)&As[buf][k][ty * 8 + 4]; a[4]=v.x; a[5]=v.y; a[6]=v.z; a[7]=v.w;
            v = *(const float4*)&Bs[buf][k][tx * 8];     b[0]=v.x; b[1]=v.y; b[2]=v.z; b[3]=v.w;
            v = *(const float4*)&Bs[buf][k][tx * 8 + 4]; b[4]=v.x; b[5]=v.y; b[6]=v.z; b[7]=v.w;
#pragma unroll
            for (int i = 0; i < 8; i++)
#pragma unroll
                for (int j = 0; j < 8; j++)
                    acc[i][j] = fmaf(a[i], b[j], acc[i][j]);
        }

        if (has_next) {
            const int nb = buf ^ 1;
            st_trans4(&As[nb][a_k][a_m],      BM + 4, pa0);
            st_trans4(&As[nb][a_k][a_m + 64], BM + 4, pa1);
            if (TRANSB) {
                st_trans4(&Bs[nb][t_k][t_n],      BN + 4, pb0);
                st_trans4(&Bs[nb][t_k][t_n + 64], BN + 4, pb1);
            } else {
                *(float4*)&Bs[nb][b_k][b_n]     = pb0;
                *(float4*)&Bs[nb][b_k + 8][b_n] = pb1;
            }
            __syncthreads();
        }
        buf ^= 1;
    }

    // ---- epilogue ---------------------------------------------------------
#pragma unroll
    for (int i = 0; i < 8; i++) {
        float4 v0 = make_float4(acc[i][0], acc[i][1], acc[i][2], acc[i][3]);
        float4 v1 = make_float4(acc[i][4], acc[i][5], acc[i][6], acc[i][7]);
        size_t off = (size_t)(bm + ty * 8 + i) * N + bn + tx * 8;
        *(float4*)&Cb[off]     = v0;
        *(float4*)&Cb[off + 4] = v1;
    }
}

// In-place row softmax over 2048 columns. One block (256 threads) per row.
__global__ void softmax_kernel(float* __restrict__ S)
{
    const int NCOL = 2048;
    float* row = S + (size_t)blockIdx.x * NCOL;
    const int tid = threadIdx.x;

    float v[8];
    float m = -1e30f;
#pragma unroll
    for (int i = 0; i < 8; i++) {
        v[i] = row[tid + 256 * i];
        m = fmaxf(m, v[i]);
    }
#pragma unroll
    for (int off = 16; off; off >>= 1)
        m = fmaxf(m, __shfl_xor_sync(0xffffffffu, m, off));

    __shared__ float redm[8];
    __shared__ float reds[8];
    if ((tid & 31) == 0) redm[tid >> 5] = m;
    __syncthreads();
#pragma unroll
    for (int j = 0; j < 8; j++) m = fmaxf(m, redm[j]);

    float s = 0.0f;
#pragma unroll
    for (int i = 0; i < 8; i++) {
        v[i] = __expf(v[i] - m);
        s += v[i];
    }
#pragma unroll
    for (int off = 16; off; off >>= 1)
        s += __shfl_xor_sync(0xffffffffu, s, off);
    if ((tid & 31) == 0) reds[tid >> 5] = s;
    __syncthreads();
    s = 0.0f;
#pragma unroll
    for (int j = 0; j < 8; j++) s += reds[j];

    const float inv = 1.0f / s;
#pragma unroll
    for (int i = 0; i < 8; i++)
        row[tid + 256 * i] = v[i] * inv;
}

extern "C" void kernel_launch(void* const* d_in, const int* in_sizes, int n_in,
                              void* d_out, int out_size)
{
    const float* S1 = (const float*)d_in[0];
    const float* S2 = (const float*)d_in[1];
    const float* W1 = (const float*)d_in[2];
    const float* W2 = (const float*)d_in[3];
    float* out = (float*)d_out;

    float* Q = nullptr;
    float* P = nullptr;
    cudaGetSymbolAddress((void**)&Q, g_Q);
    cudaGetSymbolAddress((void**)&P, g_P);

    const long long bs = 2048LL * 1024;   // per-batch S / Q / out stride
    const long long ss = 2048LL * 2048;   // per-batch scores stride

    dim3 blk(256);

    // -------- Path 1: out1 = softmax((S1 W1) S2^T) S2 ----------------------
    // Q = S1 @ W1   (fold batch into M: 16384 x 1024 x 1024)
    sgemm_kernel<false><<<dim3(1024 / BN, 16384 / BM, 1), blk>>>(
        S1, W1, Q, 16384, 1024, 1024, 0, 0, 0);
    // P[b] = Q[b] @ S2[b]^T   (2048 x 2048 x 1024, batch 8)
    sgemm_kernel<true><<<dim3(2048 / BN, 2048 / BM, 8), blk>>>(
        Q, S2, P, 2048, 2048, 1024, bs, bs, ss);
    softmax_kernel<<<8 * 2048, 256>>>(P);
    // out1[b] = P[b] @ S2[b]   (2048 x 1024 x 2048, batch 8)
    sgemm_kernel<false><<<dim3(1024 / BN, 2048 / BM, 8), blk>>>(
        P, S2, out, 2048, 1024, 2048, ss, bs, bs);

    // -------- Path 2: out2 = softmax((S2 W2) S1^T) S1 ----------------------
    sgemm_kernel<false><<<dim3(1024 / BN, 16384 / BM, 1), blk>>>(
        S2, W2, Q, 16384, 1024, 1024, 0, 0, 0);
    sgemm_kernel<true><<<dim3(2048 / BN, 2048 / BM, 8), blk>>>(
        Q, S1, P, 2048, 2048, 1024, bs, bs, ss);
    softmax_kernel<<<8 * 2048, 256>>>(P);
    sgemm_kernel<false><<<dim3(1024 / BN, 2048 / BM, 8), blk>>>(
        P, S1, out + 8LL * bs, 2048, 1024, 2048, ss, bs, bs);
}

// round 3
// speedup vs baseline: 2.9230x; 2.9230x over previous
#include <cuda_runtime.h>
#include <cuda_bf16.h>
#include <cstdint>
#include <cstddef>

// ---------------------------------------------------------------------------
// BiAffine via mma.sync (HMMA) bf16x3 GEMMs  (target sm_100 baseline ISA).
//   Path1: Q1 = S1@W1 ; P1 = softmax(Q1 S2^T) ; out1 = P1 @ S2
//   Path2: Q2 = S2@W2 ; P2 = softmax(Q2 S1^T) ; out2 = P2 @ S1
// Every fp32 operand split into bf16 (hi, mid); each k16 step does
// hi*hi + hi*mid + mi*hi into fp32 accumulators.
// All GEMMs are C[M,N] = A[M,K] @ B[N,K]^T with K-major A and B.
// ---------------------------------------------------------------------------

#define BM 128
#define BN 128
#define BKS 64                                  // K elements per smem stage
#define STAGES 3
#define A_BYTES (BM * 128)                      // 16384 (128 rows x 128B)
#define B_BYTES (BN * 128)                      // 16384
#define STAGE_BYTES (2 * A_BYTES + 2 * B_BYTES) // 65536
#define SMEM_TOTAL (STAGES * STAGE_BYTES + 1024)

// ---------------- device scratch (static, allocation-free) -----------------
__device__ __nv_bfloat16 g_S1h[16384LL * 1024], g_S1m[16384LL * 1024];
__device__ __nv_bfloat16 g_S2h[16384LL * 1024], g_S2m[16384LL * 1024];
__device__ __nv_bfloat16 g_S1Th[8LL * 1024 * 2048], g_S1Tm[8LL * 1024 * 2048];
__device__ __nv_bfloat16 g_S2Th[8LL * 1024 * 2048], g_S2Tm[8LL * 1024 * 2048];
__device__ __nv_bfloat16 g_W1Th[1024 * 1024], g_W1Tm[1024 * 1024];
__device__ __nv_bfloat16 g_W2Th[1024 * 1024], g_W2Tm[1024 * 1024];
__device__ __nv_bfloat16 g_Qh[16384LL * 1024], g_Qm[16384LL * 1024];
__device__ float         g_P[8LL * 2048 * 2048];
__device__ __nv_bfloat16 g_Ph[8LL * 2048 * 2048], g_Pm[8LL * 2048 * 2048];

// ---------------- helpers ---------------------------------------------------
__device__ __forceinline__ uint32_t smem_u32(const void* p) {
    uint32_t a;
    asm("{ .reg .u64 t; cvta.to.shared.u64 t, %1; cvt.u32.u64 %0, t; }"
        : "=r"(a) : "l"(p));
    return a;
}

__device__ __forceinline__ void ldsm4(uint32_t* r, uint32_t addr) {
    asm volatile("ldmatrix.sync.aligned.m8n8.x4.shared.b16 {%0,%1,%2,%3}, [%4];"
                 : "=r"(r[0]), "=r"(r[1]), "=r"(r[2]), "=r"(r[3]) : "r"(addr));
}

__device__ __forceinline__ void mma16816(float* c, const uint32_t* a,
                                         const uint32_t* b) {
    asm volatile(
        "mma.sync.aligned.m16n8k16.row.col.f32.bf16.bf16.f32 "
        "{%0,%1,%2,%3}, {%4,%5,%6,%7}, {%8,%9}, {%0,%1,%2,%3};"
        : "+f"(c[0]), "+f"(c[1]), "+f"(c[2]), "+f"(c[3])
        : "r"(a[0]), "r"(a[1]), "r"(a[2]), "r"(a[3]), "r"(b[0]), "r"(b[1]));
}

// split fp32 pair -> packed bf16 hi / mid
__device__ __forceinline__ uint32_t pack_split(float x0, float x1, uint32_t& mid_pack) {
    __nv_bfloat16 h0 = __float2bfloat16(x0);
    __nv_bfloat16 h1 = __float2bfloat16(x1);
    __nv_bfloat16 m0 = __float2bfloat16(x0 - __bfloat162float(h0));
    __nv_bfloat16 m1 = __float2bfloat16(x1 - __bfloat162float(h1));
    mid_pack = (uint32_t)__bfloat16_as_ushort(m0) |
               ((uint32_t)__bfloat16_as_ushort(m1) << 16);
    return (uint32_t)__bfloat16_as_ushort(h0) |
           ((uint32_t)__bfloat16_as_ushort(h1) << 16);
}

// smem address of (row, 16B-chunk kc) inside a 128B-row SW128-swizzled region
__device__ __forceinline__ uint32_t sw_addr(uint32_t region, int r, int kc) {
    return region + (uint32_t)(r * 128 + ((kc ^ (r & 7)) * 16));
}

// copy R x 64 bf16 (R x 128B rows) global -> smem with SW128 swizzle, cp.async
template <int R>
__device__ __forceinline__ void load_tile(uint32_t sdst, const __nv_bfloat16* g,
                                          long long ld, int tid) {
#pragma unroll
    for (int i = 0; i < (R * 8) / 256; i++) {
        int c = tid + i * 256;
        int row = c >> 3, col = c & 7;
        uint32_t off = (uint32_t)(row * 128 + col * 16);
        uint32_t sw  = off ^ ((off >> 3) & 0x70);
        const void* src = g + (long long)row * ld + col * 8;
        asm volatile("cp.async.cg.shared.global [%0], [%1], 16;"
                     :: "r"(sdst + sw), "l"(src) : "memory");
    }
}

__device__ __forceinline__ void issue_stage_loads(
    uint32_t base,
    const __nv_bfloat16* pAh, const __nv_bfloat16* pAm,
    const __nv_bfloat16* pBh, const __nv_bfloat16* pBm,
    long long aoff, long long boff, int K, int tid)
{
    load_tile<BM>(base,                       pAh + aoff, K, tid);
    load_tile<BM>(base + A_BYTES,             pAm + aoff, K, tid);
    load_tile<BN>(base + 2 * A_BYTES,         pBh + boff, K, tid);
    load_tile<BN>(base + 2 * A_BYTES + B_BYTES, pBm + boff, K, tid);
    asm volatile("cp.async.commit_group;" ::: "memory");
}

// ---------------- HMMA GEMM: C[M,N] = A[M,K] @ B[N,K]^T ---------------------
// EPI 0: fp32 C.  EPI 1: bf16 (hi, mid) split C.
template <int EPI>
__global__ void __launch_bounds__(256, 1)
gemm_mma(const __nv_bfloat16* __restrict__ Ah, const __nv_bfloat16* __restrict__ Am,
         const __nv_bfloat16* __restrict__ Bh, const __nv_bfloat16* __restrict__ Bm,
         float* __restrict__ Cf, __nv_bfloat16* __restrict__ Ch,
         __nv_bfloat16* __restrict__ Cm,
         int M, int N, int K,
         long long sA, long long sB, long long sC)
{
    extern __shared__ char smem_raw[];
    const int tid  = threadIdx.x;
    const int wid  = tid >> 5;
    const int lane = tid & 31;
    const uint32_t sb = (smem_u32(smem_raw) + 1023u) & ~1023u;

    const long long z = blockIdx.z;
    const __nv_bfloat16* pAh = Ah + z * sA;
    const __nv_bfloat16* pAm = Am + z * sA;
    const __nv_bfloat16* pBh = Bh + z * sB;
    const __nv_bfloat16* pBm = Bm + z * sB;

    const int bm = blockIdx.y * BM;
    const int bn = blockIdx.x * BN;
    const int nt = K / BKS;

    // warp tiling: 4 (m) x 2 (n); warp tile 32 x 64
    const int wm = (wid & 3) * 32;
    const int wn = (wid >> 2) * 64;

    float acc[2][8][4];
#pragma unroll
    for (int i = 0; i < 2; i++)
#pragma unroll
        for (int j = 0; j < 8; j++)
#pragma unroll
            for (int v = 0; v < 4; v++) acc[i][j][v] = 0.0f;

    // ldmatrix per-lane row/chunk offsets
    const int la_r  = (lane & 7) + 8 * ((lane >> 3) & 1); // A row offset
    const int la_kc = lane >> 4;                          // A chunk offset
    const int lb_r  = (lane & 7) + 8 * (lane >> 4);       // B row offset
    const int lb_kc = (lane >> 3) & 1;                    // B chunk offset

    // prologue: stages 0, 1
    issue_stage_loads(sb, pAh, pAm, pBh, pBm,
                      (long long)bm * K, (long long)bn * K, K, tid);
    issue_stage_loads(sb + STAGE_BYTES, pAh, pAm, pBh, pBm,
                      (long long)bm * K + BKS, (long long)bn * K + BKS, K, tid);

    for (int t = 0; t < nt; t++) {
        if (t + 1 < nt) asm volatile("cp.async.wait_group 1;" ::: "memory");
        else            asm volatile("cp.async.wait_group 0;" ::: "memory");
        __syncthreads();

        if (t + 2 < nt)
            issue_stage_loads(sb + (uint32_t)((t + 2) % STAGES) * STAGE_BYTES,
                              pAh, pAm, pBh, pBm,
                              (long long)bm * K + (long long)(t + 2) * BKS,
                              (long long)bn * K + (long long)(t + 2) * BKS, K, tid);

        const uint32_t stg = sb + (uint32_t)(t % STAGES) * STAGE_BYTES;
        const uint32_t rAh = stg;
        const uint32_t rAm = stg + A_BYTES;
        const uint32_t rBh = stg + 2 * A_BYTES;
        const uint32_t rBm = stg + 2 * A_BYTES + B_BYTES;

#pragma unroll
        for (int ks = 0; ks < 4; ks++) {
            const int kc = ks * 2;
            uint32_t ah[2][4], am[2][4], bhf[4][4], bmf[4][4];
#pragma unroll
            for (int mt = 0; mt < 2; mt++) {
                const int r = wm + mt * 16 + la_r;
                ldsm4(ah[mt], sw_addr(rAh, r, kc + la_kc));
                ldsm4(am[mt], sw_addr(rAm, r, kc + la_kc));
            }
#pragma unroll
            for (int np = 0; np < 4; np++) {
                const int r = wn + np * 16 + lb_r;
                ldsm4(bhf[np], sw_addr(rBh, r, kc + lb_kc));
                ldsm4(bmf[np], sw_addr(rBm, r, kc + lb_kc));
            }
#pragma unroll
            for (int mt = 0; mt < 2; mt++)
#pragma unroll
                for (int ntile = 0; ntile < 8; ntile++) {
                    const uint32_t* bh = &bhf[ntile >> 1][(ntile & 1) * 2];
                    const uint32_t* bm2 = &bmf[ntile >> 1][(ntile & 1) * 2];
                    mma16816(acc[mt][ntile], ah[mt], bh);
                    mma16816(acc[mt][ntile], ah[mt], bm2);
                    mma16816(acc[mt][ntile], am[mt], bh);
                }
        }
    }

    // ---- epilogue ---------------------------------------------------------
    const int g = lane >> 2;
    const int q = lane & 3;
#pragma unroll
    for (int mt = 0; mt < 2; mt++) {
#pragma unroll
        for (int ntile = 0; ntile < 8; ntile++) {
            const int row0 = bm + wm + mt * 16 + g;
            const int col  = bn + wn + ntile * 8 + 2 * q;
            float* a = acc[mt][ntile];
            if (EPI == 0) {
                float* dst = Cf + z * sC;
                *(float2*)&dst[(long long)row0 * N + col] = make_float2(a[0], a[1]);
                *(float2*)&dst[(long long)(row0 + 8) * N + col] = make_float2(a[2], a[3]);
            } else {
                __nv_bfloat16* dh = Ch + z * sC;
                __nv_bfloat16* dm = Cm + z * sC;
                uint32_t m0, m1;
                uint32_t h0 = pack_split(a[0], a[1], m0);
                uint32_t h1 = pack_split(a[2], a[3], m1);
                *(uint32_t*)&dh[(long long)row0 * N + col] = h0;
                *(uint32_t*)&dm[(long long)row0 * N + col] = m0;
                *(uint32_t*)&dh[(long long)(row0 + 8) * N + col] = h1;
                *(uint32_t*)&dm[(long long)(row0 + 8) * N + col] = m1;
            }
        }
    }
}

// ---------------- elementwise fp32 -> (hi, mid) bf16 ------------------------
__global__ void decomp_kernel(const float4* __restrict__ X, uint2* __restrict__ H,
                              uint2* __restrict__ Mo, int n4)
{
    int i = blockIdx.x * blockDim.x + threadIdx.x;
    if (i >= n4) return;
    float4 v = X[i];
    uint32_t m0, m1;
    uint32_t h0 = pack_split(v.x, v.y, m0);
    uint32_t h1 = pack_split(v.z, v.w, m1);
    H[i]  = make_uint2(h0, h1);
    Mo[i] = make_uint2(m0, m1);
}

// ---------------- transpose + split: out[c][r] = in[r][c] -------------------
__global__ void decompT_kernel(const float* __restrict__ X,
                               __nv_bfloat16* __restrict__ H,
                               __nv_bfloat16* __restrict__ Mo,
                               int R, int C, long long sIn, long long sOut)
{
    __shared__ float tile[32][33];
    const int c0 = blockIdx.x * 32, r0 = blockIdx.y * 32;
    const float* Xb = X + (long long)blockIdx.z * sIn;
    const int tx = threadIdx.x, ty = threadIdx.y;
#pragma unroll
    for (int i = 0; i < 32; i += 8)
        tile[ty + i][tx] = Xb[(long long)(r0 + ty + i) * C + c0 + tx];
    __syncthreads();
#pragma unroll
    for (int i = 0; i < 32; i += 8) {
        float v = tile[tx][ty + i];
        long long o = (long long)blockIdx.z * sOut +
                      (long long)(c0 + ty + i) * R + (r0 + tx);
        __nv_bfloat16 h = __float2bfloat16(v);
        H[o]  = h;
        Mo[o] = __float2bfloat16(v - __bfloat162float(h));
    }
}

// ---------------- softmax over 2048 cols -> (hi, mid) bf16 ------------------
__global__ void softmax_split_kernel(const float* __restrict__ S,
                                     __nv_bfloat16* __restrict__ H,
                                     __nv_bfloat16* __restrict__ Mo)
{
    const int NCOL = 2048;
    const long long rowoff = (long long)blockIdx.x * NCOL;
    const float* row = S + rowoff;
    const int tid = threadIdx.x;

    float v[8];
    float m = -1e30f;
#pragma unroll
    for (int i = 0; i < 8; i++) {
        v[i] = row[tid + 256 * i];
        m = fmaxf(m, v[i]);
    }
#pragma unroll
    for (int off = 16; off; off >>= 1)
        m = fmaxf(m, __shfl_xor_sync(0xffffffffu, m, off));

    __shared__ float redm[8];
    __shared__ float reds[8];
    if ((tid & 31) == 0) redm[tid >> 5] = m;
    __syncthreads();
#pragma unroll
    for (int j = 0; j < 8; j++) m = fmaxf(m, redm[j]);

    float s = 0.0f;
#pragma unroll
    for (int i = 0; i < 8; i++) {
        v[i] = __expf(v[i] - m);
        s += v[i];
    }
#pragma unroll
    for (int off = 16; off; off >>= 1)
        s += __shfl_xor_sync(0xffffffffu, s, off);
    if ((tid & 31) == 0) reds[tid >> 5] = s;
    __syncthreads();
    s = 0.0f;
#pragma unroll
    for (int j = 0; j < 8; j++) s += reds[j];

    const float inv = 1.0f / s;
#pragma unroll
    for (int i = 0; i < 8; i++) {
        float p = v[i] * inv;
        __nv_bfloat16 h = __float2bfloat16(p);
        long long o = rowoff + tid + 256 * i;
        H[o]  = h;
        Mo[o] = __float2bfloat16(p - __bfloat162float(h));
    }
}

// ---------------------------------------------------------------------------
extern "C" void kernel_launch(void* const* d_in, const int* in_sizes, int n_in,
                              void* d_out, int out_size)
{
    const float* S1 = (const float*)d_in[0];
    const float* S2 = (const float*)d_in[1];
    const float* W1 = (const float*)d_in[2];
    const float* W2 = (const float*)d_in[3];
    float* out = (float*)d_out;

    __nv_bfloat16 *s1h, *s1m, *s2h, *s2m, *s1th, *s1tm, *s2th, *s2tm;
    __nv_bfloat16 *w1th, *w1tm, *w2th, *w2tm, *qh, *qm, *ph, *pm;
    float* P;
    cudaGetSymbolAddress((void**)&s1h, g_S1h);  cudaGetSymbolAddress((void**)&s1m, g_S1m);
    cudaGetSymbolAddress((void**)&s2h, g_S2h);  cudaGetSymbolAddress((void**)&s2m, g_S2m);
    cudaGetSymbolAddress((void**)&s1th, g_S1Th); cudaGetSymbolAddress((void**)&s1tm, g_S1Tm);
    cudaGetSymbolAddress((void**)&s2th, g_S2Th); cudaGetSymbolAddress((void**)&s2tm, g_S2Tm);
    cudaGetSymbolAddress((void**)&w1th, g_W1Th); cudaGetSymbolAddress((void**)&w1tm, g_W1Tm);
    cudaGetSymbolAddress((void**)&w2th, g_W2Th); cudaGetSymbolAddress((void**)&w2tm, g_W2Tm);
    cudaGetSymbolAddress((void**)&qh, g_Qh);    cudaGetSymbolAddress((void**)&qm, g_Qm);
    cudaGetSymbolAddress((void**)&ph, g_Ph);    cudaGetSymbolAddress((void**)&pm, g_Pm);
    cudaGetSymbolAddress((void**)&P, g_P);

    cudaFuncSetAttribute(gemm_mma<0>, cudaFuncAttributeMaxDynamicSharedMemorySize, SMEM_TOTAL);
    cudaFuncSetAttribute(gemm_mma<1>, cudaFuncAttributeMaxDynamicSharedMemorySize, SMEM_TOTAL);

    const long long bs = 2048LL * 1024;   // per-batch S/Q/out stride
    const long long ss = 2048LL * 2048;   // per-batch scores stride
    const long long ts = 1024LL * 2048;   // per-batch S^T stride
    const int n4 = 16384 * 1024 / 4;

    // ---- decompositions ---------------------------------------------------
    decomp_kernel<<<n4 / 256, 256>>>((const float4*)S1, (uint2*)s1h, (uint2*)s1m, n4);
    decomp_kernel<<<n4 / 256, 256>>>((const float4*)S2, (uint2*)s2h, (uint2*)s2m, n4);
    decompT_kernel<<<dim3(32, 32, 1), dim3(32, 8)>>>(W1, w1th, w1tm, 1024, 1024, 0, 0);
    decompT_kernel<<<dim3(32, 32, 1), dim3(32, 8)>>>(W2, w2th, w2tm, 1024, 1024, 0, 0);
    decompT_kernel<<<dim3(32, 64, 8), dim3(32, 8)>>>(S1, s1th, s1tm, 2048, 1024, bs, ts);
    decompT_kernel<<<dim3(32, 64, 8), dim3(32, 8)>>>(S2, s2th, s2tm, 2048, 1024, bs, ts);

    // ---- Path 1 -----------------------------------------------------------
    gemm_mma<1><<<dim3(1024 / BN, 16384 / BM, 1), 256, SMEM_TOTAL>>>(
        s1h, s1m, w1th, w1tm, nullptr, qh, qm, 16384, 1024, 1024, 0, 0, 0);
    gemm_mma<0><<<dim3(2048 / BN, 2048 / BM, 8), 256, SMEM_TOTAL>>>(
        qh, qm, s2h, s2m, P, nullptr, nullptr, 2048, 2048, 1024, bs, bs, ss);
    softmax_split_kernel<<<8 * 2048, 256>>>(P, ph, pm);
    gemm_mma<0><<<dim3(1024 / BN, 2048 / BM, 8), 256, SMEM_TOTAL>>>(
        ph, pm, s2th, s2tm, out, nullptr, nullptr, 2048, 1024, 2048, ss, ts, bs);

    // ---- Path 2 -----------------------------------------------------------
    gemm_mma<1><<<dim3(1024 / BN, 16384 / BM, 1), 256, SMEM_TOTAL>>>(
        s2h, s2m, w2th, w2tm, nullptr, qh, qm, 16384, 1024, 1024, 0, 0, 0);
    gemm_mma<0><<<dim3(2048 / BN, 2048 / BM, 8), 256, SMEM_TOTAL>>>(
        qh, qm, s1h, s1m, P, nullptr, nullptr, 2048, 2048, 1024, bs, bs, ss);
    softmax_split_kernel<<<8 * 2048, 256>>>(P, ph, pm);
    gemm_mma<0><<<dim3(1024 / BN, 2048 / BM, 8), 256, SMEM_TOTAL>>>(
        ph, pm, s1th, s1tm, out + 8LL * bs, nullptr, nullptr, 2048, 1024, 2048, ss, ts, bs);
}